// round 12
// baseline (speedup 1.0000x reference)
#include <cuda_runtime.h>
#include <cuda_bf16.h>
#include <float.h>
#include <limits.h>

#define FULL 0xFFFFFFFFu

static constexpr int B = 4;
static constexpr int N = 8192;
static constexpr int M = 2048;
static constexpr int F = 256;
static constexpr int K = 16;
static constexpr int OUTC = 3 + F;  // 259
static constexpr int QPB = 8;       // queries per knn block (2 warps each)

static constexpr int KNNB = (B * M) / QPB;             // 1024 knn blocks
static constexpr int TRB  = B * (F / 32) * (N / 128);  // 2048 transpose tiles

// Scratch (device globals — no allocation allowed)
__device__ float g_featT[(size_t)B * N * F];   // 32MB transposed features (B,N,F)
__device__ int   g_idx[(size_t)B * M * K];
__device__ float g_w[(size_t)B * M * K];

// ---------------------------------------------------------------------------
// Fused kernel, 512-thread blocks.
//   blocks [0, 1024):      KNN — warp PAIR per query. Each warp scans 4096
//                          points (alternate 32-pt tiles of the block-staged
//                          chunk) keeping its own top-16; ends with a
//                          16-candidate merge. All ordering is (key, orig
//                          index) lexicographic — proven bit-exact vs
//                          jax.lax.top_k in R10 — so the split scan cannot
//                          change the selected set.
//   blocks [1024, 3072):   feature transpose (B,F,N)->(B,N,F), co-resident
//                          DRAM streaming overlapped with the smem-bound KNN.
// ---------------------------------------------------------------------------
__global__ __launch_bounds__(512) void fused_knn_transpose(
    const float* __restrict__ pc,     // (B,3,N)
    const float* __restrict__ qc,     // (B,3,M)
    const float* __restrict__ temperature,
    const float* __restrict__ feat,   // (B,F,N)
    float* __restrict__ out)          // (B,259,M)
{
    __shared__ __align__(16) unsigned char smem_raw[32768];
    __shared__ float s_mkd[QPB][16];
    __shared__ int   s_mki[QPB][16];

    if (blockIdx.x < KNNB) {
        // ===================== KNN =====================
        float4* s_pts = (float4*)smem_raw;    // 2048 * 16B = 32KB

        const int tid    = threadIdx.x;
        const int lane   = tid & 31;
        const int wid    = tid >> 5;
        const int qlocal = wid >> 1;            // 0..7
        const int parity = wid & 1;             // which half of tiles
        const int b      = blockIdx.x >> 8;     // 256 blocks per batch
        const int m      = ((blockIdx.x & 255) << 3) + qlocal;

        const float* pcb = pc + (size_t)b * 3 * N;

        const float qx = qc[((size_t)b * 3 + 0) * M + m];
        const float qy = qc[((size_t)b * 3 + 1) * M + m];
        const float qz = qc[((size_t)b * 3 + 2) * M + m];
        const float ax = -2.0f * qx, ay = -2.0f * qy, az = -2.0f * qz;

        // warp-distributed list sorted by (key, orig index); lane i = i-th best
        float kd = FLT_MAX;
        int   ki = INT_MAX;
        float thr    = FLT_MAX;   // 16th-best key
        int   thrIdx = INT_MAX;   // its original index

        // insert candidates (s, idx) per lane; ordering (key, index)
        auto insert = [&](float s, int idx) {
            bool acc = (s < thr) || (s == thr && idx < thrIdx);
            unsigned mask = __ballot_sync(FULL, acc);
            if (mask) {
                do {
                    int src = __ffs(mask) - 1;
                    mask &= mask - 1;
                    float cd = __shfl_sync(FULL, s, src);
                    int   ci = __shfl_sync(FULL, idx, src);
                    bool better = (kd < cd) || (kd == cd && ki < ci);
                    int pos = __popc(__ballot_sync(FULL, better));
                    float ud = __shfl_up_sync(FULL, kd, 1);
                    int   ui = __shfl_up_sync(FULL, ki, 1);
                    if (lane >= pos) {
                        kd = (lane == pos) ? cd : ud;
                        ki = (lane == pos) ? ci : ui;
                    }
                } while (mask);
                thr    = __shfl_sync(FULL, kd, 15);
                thrIdx = __shfl_sync(FULL, ki, 15);
            }
        };

        for (int c = 0; c < 4; ++c) {
            __syncthreads();
            for (int i = tid; i < 2048; i += 512) {
                int n = c * 2048 + i;
                float x = pcb[n];
                float y = pcb[N + n];
                float z = pcb[2 * N + n];
                s_pts[i] = make_float4(x, y, z, fmaf(x, x, fmaf(y, y, z * z)));
            }
            __syncthreads();

            // this warp scans tiles t = parity, parity+2, ... (32 tiles/chunk)
            #pragma unroll 4
            for (int t = parity; t < 64; t += 2) {
                float4 p = s_pts[t * 32 + lane];
                float s = fmaf(ax, p.x, p.w);
                s = fmaf(ay, p.y, s);
                s = fmaf(az, p.z, s);
                insert(s, c * 2048 + t * 32 + lane);
            }
        }

        // -------- merge the two half-lists (exact under (key,index) order) --
        if (parity == 1 && lane < 16) {
            s_mkd[qlocal][lane] = kd;
            s_mki[qlocal][lane] = ki;
        }
        __syncthreads();

        if (parity == 0) {
            float cs = (lane < 16) ? s_mkd[qlocal][lane] : FLT_MAX;
            int   cix = (lane < 16) ? s_mki[qlocal][lane] : INT_MAX;
            insert(cs, cix);

            // softmax over the 16 best (shift-invariant in s) — R1 formula
            float tv = *temperature;
            float sigma = fmaxf(tv * tv, 1e-4f);
            float inv_sigma = 1.0f / sigma;
            float s0 = __shfl_sync(FULL, kd, 0);
            float ev = (lane < K) ? __expf((s0 - kd) * inv_sigma) : 0.0f;
            float sum = ev;
            #pragma unroll
            for (int o = 16; o; o >>= 1) sum += __shfl_xor_sync(FULL, sum, o);
            float w = ev / sum;

            // projected points (lanes >= 16 contribute w = 0; guard ki)
            int kiq = (lane < K) ? ki : 0;
            float px = pcb[kiq];
            float py = pcb[N + kiq];
            float pz = pcb[2 * N + kiq];
            float sx = w * px, sy = w * py, sz = w * pz;
            #pragma unroll
            for (int o = 16; o; o >>= 1) {
                sx += __shfl_xor_sync(FULL, sx, o);
                sy += __shfl_xor_sync(FULL, sy, o);
                sz += __shfl_xor_sync(FULL, sz, o);
            }
            if (lane == 0) {
                out[((size_t)b * OUTC + 0) * M + m] = sx;
                out[((size_t)b * OUTC + 1) * M + m] = sy;
                out[((size_t)b * OUTC + 2) * M + m] = sz;
            }
            if (lane < K) {
                size_t gq = (size_t)b * M + m;
                g_idx[gq * K + lane] = ki;
                g_w[gq * K + lane]   = w;
            }
        }
    } else {
        // ===================== transpose ==============
        // (B,F,N) -> (B,N,F); tile = 32 f x 128 n per block
        float (*tile)[129] = (float (*)[129])smem_raw;   // 32*129*4 = 16512B

        int t  = blockIdx.x - KNNB;         // 0..2047
        int b  = t >> 9;                    // 512 tiles per batch
        int r  = t & 511;
        int fb = r >> 6;                    // 0..7  (f block of 32)
        int nb = r & 63;                    // 0..63 (n block of 128)

        int tx = threadIdx.x & 127;         // n within tile
        int ty = threadIdx.x >> 7;          // 0..3
        const float* src = feat + ((size_t)b * F + fb * 32) * N + nb * 128;
        #pragma unroll
        for (int j = ty; j < 32; j += 4)
            tile[j][tx] = src[(size_t)j * N + tx];
        __syncthreads();

        int cx = threadIdx.x & 31;          // f within tile
        int cy = threadIdx.x >> 5;          // 0..15
        float* dst = g_featT + ((size_t)b * N + nb * 128) * F + fb * 32;
        #pragma unroll
        for (int j = cy; j < 128; j += 16)
            dst[(size_t)j * F + cx] = tile[cx][j];
    }
}

// ---------------------------------------------------------------------------
// Feature propagation (R11-proven): 1024 threads = 32 warps = 16 queries,
// 2 warps per query (each gathers 128 of 256 features — 2x MLP on the
// latency/L2-bound gather). Near the chip L2 LTS cap at fp32.
// ---------------------------------------------------------------------------
__global__ __launch_bounds__(1024) void feat_kernel(float* __restrict__ out)
{
    __shared__ float so[16][260];

    const int lane   = threadIdx.x & 31;
    const int wid    = threadIdx.x >> 5;       // 0..31
    const int qlocal = wid >> 1;               // 0..15
    const int half   = wid & 1;                // 0/1 -> 128 features each
    const int b      = blockIdx.x >> 7;        // 128 blocks per batch
    const int m0     = (blockIdx.x & 127) * 16;
    const int m      = m0 + qlocal;
    const size_t gq  = (size_t)b * M + m;

    int   iv = 0;
    float wv = 0.0f;
    if (lane < K) {
        iv = g_idx[gq * K + lane];
        wv = g_w[gq * K + lane];
    }

    float4 acc = make_float4(0.f, 0.f, 0.f, 0.f);
    #pragma unroll
    for (int j = 0; j < K; ++j) {
        float wj = __shfl_sync(FULL, wv, j);
        int   ij = __shfl_sync(FULL, iv, j);
        const float4* base =
            (const float4*)(g_featT + ((size_t)b * N + ij) * F + half * 128);
        float4 u = base[lane];
        acc.x = fmaf(wj, u.x, acc.x);
        acc.y = fmaf(wj, u.y, acc.y);
        acc.z = fmaf(wj, u.z, acc.z);
        acc.w = fmaf(wj, u.w, acc.w);
    }

    *(float4*)&so[qlocal][half * 128 + 4 * lane] = acc;
    __syncthreads();

    // warp wid writes f rows [wid*8, wid*8+8); lanes: 2 f x 16 mLocal
    #pragma unroll
    for (int r = 0; r < 4; ++r) {
        int f  = wid * 8 + r * 2 + (lane >> 4);
        int ml = lane & 15;
        out[((size_t)b * OUTC + 3 + f) * M + m0 + ml] = so[ml][f];
    }
}

// ---------------------------------------------------------------------------
extern "C" void kernel_launch(void* const* d_in, const int* in_sizes, int n_in,
                              void* d_out, int out_size)
{
    const float* pc   = (const float*)d_in[0];  // point_cloud (B,3,N)
    const float* qc   = (const float*)d_in[1];  // query_cloud (B,3,M)
    const float* feat = (const float*)d_in[2];  // point_features (B,F,N)
    const float* temp = (const float*)d_in[3];  // temperature scalar
    float* out = (float*)d_out;

    fused_knn_transpose<<<KNNB + TRB, 512>>>(pc, qc, temp, feat, out);
    feat_kernel<<<(B * M) / 16, 1024>>>(out);
}

// round 13
// speedup vs baseline: 1.7820x; 1.7820x over previous
#include <cuda_runtime.h>
#include <cuda_bf16.h>
#include <float.h>

#define FULL 0xFFFFFFFFu

static constexpr int B = 4;
static constexpr int N = 8192;
static constexpr int M = 2048;
static constexpr int F = 256;
static constexpr int K = 16;
static constexpr int OUTC = 3 + F;  // 259

static constexpr int KNNB = (B * M) / 16;              // 512 knn blocks
static constexpr int TRB  = B * (F / 32) * (N / 128);  // 2048 transpose tiles

// Scratch (device globals — no allocation allowed)
__device__ float g_featT[(size_t)B * N * F];   // 32MB transposed features (B,N,F)
__device__ int   g_idx[(size_t)B * M * K];
__device__ float g_w[(size_t)B * M * K];

// ---------------------------------------------------------------------------
// Fused kernel (R9-proven, byte-for-byte): 512-thread blocks.
//   blocks [0, 512):     KNN — warp per query, brute-force scan of all 8192
//                        points in original order, key s = |p|^2 - 2 q.p.
//   blocks [512, 2560):  feature transpose (B,F,N)->(B,N,F), co-resident
//                        DRAM streaming overlapped with the smem-bound KNN.
// ---------------------------------------------------------------------------
__global__ __launch_bounds__(512) void fused_knn_transpose(
    const float* __restrict__ pc,     // (B,3,N)
    const float* __restrict__ qc,     // (B,3,M)
    const float* __restrict__ temperature,
    const float* __restrict__ feat,   // (B,F,N)
    float* __restrict__ out)          // (B,259,M)
{
    __shared__ __align__(16) unsigned char smem_raw[32768];

    if (blockIdx.x < KNNB) {
        // ===================== KNN (R9-exact) =====================
        float4* s_pts = (float4*)smem_raw;    // 2048 * 16B = 32KB

        const int tid  = threadIdx.x;
        const int lane = tid & 31;
        const int wid  = tid >> 5;
        const int b    = blockIdx.x >> 7;              // 128 blocks per batch
        const int m    = ((blockIdx.x & 127) << 4) + wid;

        const float* pcb = pc + (size_t)b * 3 * N;

        const float qx = qc[((size_t)b * 3 + 0) * M + m];
        const float qy = qc[((size_t)b * 3 + 1) * M + m];
        const float qz = qc[((size_t)b * 3 + 2) * M + m];
        const float ax = -2.0f * qx, ay = -2.0f * qy, az = -2.0f * qz;

        float kd = FLT_MAX;   // warp-sorted list: lane i = i-th smallest
        int   ki = 0;
        float thr = FLT_MAX;  // lazy copy of element 15 (16th smallest)

        for (int c = 0; c < 4; ++c) {
            __syncthreads();
            for (int i = tid; i < 2048; i += 512) {
                int n = c * 2048 + i;
                float x = pcb[n];
                float y = pcb[N + n];
                float z = pcb[2 * N + n];
                s_pts[i] = make_float4(x, y, z, fmaf(x, x, fmaf(y, y, z * z)));
            }
            __syncthreads();

            #pragma unroll 4
            for (int t = 0; t < 64; ++t) {
                float4 p = s_pts[t * 32 + lane];
                float s = fmaf(ax, p.x, p.w);
                s = fmaf(ay, p.y, s);
                s = fmaf(az, p.z, s);
                unsigned mask = __ballot_sync(FULL, s < thr);
                if (mask) {
                    int nbase = c * 2048 + t * 32;
                    do {
                        int src = __ffs(mask) - 1;
                        mask &= mask - 1;
                        float cd = __shfl_sync(FULL, s, src);
                        int   cn = nbase + src;
                        int pos = __popc(__ballot_sync(FULL, kd < cd));
                        float ud = __shfl_up_sync(FULL, kd, 1);
                        int   ui = __shfl_up_sync(FULL, ki, 1);
                        if (lane >= pos) {
                            kd = (lane == pos) ? cd : ud;
                            ki = (lane == pos) ? cn : ui;
                        }
                    } while (mask);
                    thr = __shfl_sync(FULL, kd, 15);
                }
            }
        }

        // softmax over the 16 smallest (shift-invariant in s)
        float tv = *temperature;
        float sigma = fmaxf(tv * tv, 1e-4f);
        float inv_sigma = 1.0f / sigma;
        float s0 = __shfl_sync(FULL, kd, 0);
        float ev = (lane < K) ? __expf((s0 - kd) * inv_sigma) : 0.0f;
        float sum = ev;
        #pragma unroll
        for (int o = 16; o; o >>= 1) sum += __shfl_xor_sync(FULL, sum, o);
        float w = ev / sum;

        // projected points: sum_k w_k * p_k (lanes >= 16 contribute w = 0)
        float px = pcb[ki];
        float py = pcb[N + ki];
        float pz = pcb[2 * N + ki];
        float sx = w * px, sy = w * py, sz = w * pz;
        #pragma unroll
        for (int o = 16; o; o >>= 1) {
            sx += __shfl_xor_sync(FULL, sx, o);
            sy += __shfl_xor_sync(FULL, sy, o);
            sz += __shfl_xor_sync(FULL, sz, o);
        }
        if (lane == 0) {
            out[((size_t)b * OUTC + 0) * M + m] = sx;
            out[((size_t)b * OUTC + 1) * M + m] = sy;
            out[((size_t)b * OUTC + 2) * M + m] = sz;
        }
        if (lane < K) {
            size_t gq = (size_t)b * M + m;
            g_idx[gq * K + lane] = ki;
            g_w[gq * K + lane]   = w;
        }
    } else {
        // ===================== transpose (R9-proven) ==============
        // (B,F,N) -> (B,N,F); tile = 32 f x 128 n per block
        float (*tile)[129] = (float (*)[129])smem_raw;   // 32*129*4 = 16512B

        int t  = blockIdx.x - KNNB;         // 0..2047
        int b  = t >> 9;                    // 512 tiles per batch
        int r  = t & 511;
        int fb = r >> 6;                    // 0..7  (f block of 32)
        int nb = r & 63;                    // 0..63 (n block of 128)

        int tx = threadIdx.x & 127;         // n within tile
        int ty = threadIdx.x >> 7;          // 0..3
        const float* src = feat + ((size_t)b * F + fb * 32) * N + nb * 128;
        #pragma unroll
        for (int j = ty; j < 32; j += 4)
            tile[j][tx] = src[(size_t)j * N + tx];
        __syncthreads();

        int cx = threadIdx.x & 31;          // f within tile
        int cy = threadIdx.x >> 5;          // 0..15
        float* dst = g_featT + ((size_t)b * N + nb * 128) * F + fb * 32;
        #pragma unroll
        for (int j = cy; j < 128; j += 16)
            dst[(size_t)j * F + cx] = tile[cx][j];
    }
}

// ---------------------------------------------------------------------------
// Feature propagation (R11-proven, byte-for-byte): 1024 threads = 32 warps =
// 16 queries, 2 warps per query (each warp gathers 128 of the 256 features
// -> 2x memory-level parallelism on the latency/L2-bound gather).
// ---------------------------------------------------------------------------
__global__ __launch_bounds__(1024) void feat_kernel(float* __restrict__ out)
{
    __shared__ float so[16][260];

    const int lane   = threadIdx.x & 31;
    const int wid    = threadIdx.x >> 5;       // 0..31
    const int qlocal = wid >> 1;               // 0..15
    const int half   = wid & 1;                // 0/1 -> 128 features each
    const int b      = blockIdx.x >> 7;        // 128 blocks per batch
    const int m0     = (blockIdx.x & 127) * 16;
    const int m      = m0 + qlocal;
    const size_t gq  = (size_t)b * M + m;

    int   iv = 0;
    float wv = 0.0f;
    if (lane < K) {
        iv = g_idx[gq * K + lane];
        wv = g_w[gq * K + lane];
    }

    float4 acc = make_float4(0.f, 0.f, 0.f, 0.f);
    #pragma unroll
    for (int j = 0; j < K; ++j) {
        float wj = __shfl_sync(FULL, wv, j);
        int   ij = __shfl_sync(FULL, iv, j);
        const float4* base =
            (const float4*)(g_featT + ((size_t)b * N + ij) * F + half * 128);
        float4 u = base[lane];
        acc.x = fmaf(wj, u.x, acc.x);
        acc.y = fmaf(wj, u.y, acc.y);
        acc.z = fmaf(wj, u.z, acc.z);
        acc.w = fmaf(wj, u.w, acc.w);
    }

    *(float4*)&so[qlocal][half * 128 + 4 * lane] = acc;
    __syncthreads();

    // warp wid writes f rows [wid*8, wid*8+8); lanes: 2 f x 16 mLocal
    #pragma unroll
    for (int r = 0; r < 4; ++r) {
        int f  = wid * 8 + r * 2 + (lane >> 4);
        int ml = lane & 15;
        out[((size_t)b * OUTC + 3 + f) * M + m0 + ml] = so[ml][f];
    }
}

// ---------------------------------------------------------------------------
extern "C" void kernel_launch(void* const* d_in, const int* in_sizes, int n_in,
                              void* d_out, int out_size)
{
    const float* pc   = (const float*)d_in[0];  // point_cloud (B,3,N)
    const float* qc   = (const float*)d_in[1];  // query_cloud (B,3,M)
    const float* feat = (const float*)d_in[2];  // point_features (B,F,N)
    const float* temp = (const float*)d_in[3];  // temperature scalar
    float* out = (float*)d_out;

    fused_knn_transpose<<<KNNB + TRB, 512>>>(pc, qc, temp, feat, out);
    feat_kernel<<<(B * M) / 16, 1024>>>(out);
}

// round 14
// speedup vs baseline: 1.8528x; 1.0397x over previous
#include <cuda_runtime.h>
#include <cuda_fp16.h>
#include <float.h>

#define FULL 0xFFFFFFFFu

static constexpr int B = 4;
static constexpr int N = 8192;
static constexpr int M = 2048;
static constexpr int F = 256;
static constexpr int K = 16;
static constexpr int OUTC = 3 + F;  // 259

static constexpr int KNNB = (B * M) / 16;              // 512 knn blocks
static constexpr int TRB  = B * (F / 32) * (N / 128);  // 2048 transpose tiles

// Scratch (device globals — no allocation allowed)
__device__ __half g_featT[(size_t)B * N * F];  // 16MB transposed features (B,N,F) fp16
__device__ int    g_idx[(size_t)B * M * K];
__device__ float  g_w[(size_t)B * M * K];

// ---------------------------------------------------------------------------
// Fused kernel: 512-thread blocks.
//   blocks [0, 512):     KNN — byte-identical to R9/R13 (warp per query,
//                        brute-force scan, key s = |p|^2 - 2 q.p, warp-sorted
//                        top-16, lazy 16th-best threshold).
//   blocks [512, 2560):  feature transpose (B,F,N)->(B,N,F) with fp32->fp16
//                        convert on store — co-resident DRAM streaming
//                        overlapped with the smem-bound KNN; output bytes
//                        halved vs fp32.
// ---------------------------------------------------------------------------
__global__ __launch_bounds__(512) void fused_knn_transpose(
    const float* __restrict__ pc,     // (B,3,N)
    const float* __restrict__ qc,     // (B,3,M)
    const float* __restrict__ temperature,
    const float* __restrict__ feat,   // (B,F,N)
    float* __restrict__ out)          // (B,259,M)
{
    __shared__ __align__(16) unsigned char smem_raw[32768];

    if (blockIdx.x < KNNB) {
        // ===================== KNN (R9-exact, unchanged) =====================
        float4* s_pts = (float4*)smem_raw;    // 2048 * 16B = 32KB

        const int tid  = threadIdx.x;
        const int lane = tid & 31;
        const int wid  = tid >> 5;
        const int b    = blockIdx.x >> 7;              // 128 blocks per batch
        const int m    = ((blockIdx.x & 127) << 4) + wid;

        const float* pcb = pc + (size_t)b * 3 * N;

        const float qx = qc[((size_t)b * 3 + 0) * M + m];
        const float qy = qc[((size_t)b * 3 + 1) * M + m];
        const float qz = qc[((size_t)b * 3 + 2) * M + m];
        const float ax = -2.0f * qx, ay = -2.0f * qy, az = -2.0f * qz;

        float kd = FLT_MAX;   // warp-sorted list: lane i = i-th smallest
        int   ki = 0;
        float thr = FLT_MAX;  // lazy copy of element 15 (16th smallest)

        for (int c = 0; c < 4; ++c) {
            __syncthreads();
            for (int i = tid; i < 2048; i += 512) {
                int n = c * 2048 + i;
                float x = pcb[n];
                float y = pcb[N + n];
                float z = pcb[2 * N + n];
                s_pts[i] = make_float4(x, y, z, fmaf(x, x, fmaf(y, y, z * z)));
            }
            __syncthreads();

            #pragma unroll 4
            for (int t = 0; t < 64; ++t) {
                float4 p = s_pts[t * 32 + lane];
                float s = fmaf(ax, p.x, p.w);
                s = fmaf(ay, p.y, s);
                s = fmaf(az, p.z, s);
                unsigned mask = __ballot_sync(FULL, s < thr);
                if (mask) {
                    int nbase = c * 2048 + t * 32;
                    do {
                        int src = __ffs(mask) - 1;
                        mask &= mask - 1;
                        float cd = __shfl_sync(FULL, s, src);
                        int   cn = nbase + src;
                        int pos = __popc(__ballot_sync(FULL, kd < cd));
                        float ud = __shfl_up_sync(FULL, kd, 1);
                        int   ui = __shfl_up_sync(FULL, ki, 1);
                        if (lane >= pos) {
                            kd = (lane == pos) ? cd : ud;
                            ki = (lane == pos) ? cn : ui;
                        }
                    } while (mask);
                    thr = __shfl_sync(FULL, kd, 15);
                }
            }
        }

        // softmax over the 16 smallest (shift-invariant in s)
        float tv = *temperature;
        float sigma = fmaxf(tv * tv, 1e-4f);
        float inv_sigma = 1.0f / sigma;
        float s0 = __shfl_sync(FULL, kd, 0);
        float ev = (lane < K) ? __expf((s0 - kd) * inv_sigma) : 0.0f;
        float sum = ev;
        #pragma unroll
        for (int o = 16; o; o >>= 1) sum += __shfl_xor_sync(FULL, sum, o);
        float w = ev / sum;

        // projected points: sum_k w_k * p_k (lanes >= 16 contribute w = 0)
        float px = pcb[ki];
        float py = pcb[N + ki];
        float pz = pcb[2 * N + ki];
        float sx = w * px, sy = w * py, sz = w * pz;
        #pragma unroll
        for (int o = 16; o; o >>= 1) {
            sx += __shfl_xor_sync(FULL, sx, o);
            sy += __shfl_xor_sync(FULL, sy, o);
            sz += __shfl_xor_sync(FULL, sz, o);
        }
        if (lane == 0) {
            out[((size_t)b * OUTC + 0) * M + m] = sx;
            out[((size_t)b * OUTC + 1) * M + m] = sy;
            out[((size_t)b * OUTC + 2) * M + m] = sz;
        }
        if (lane < K) {
            size_t gq = (size_t)b * M + m;
            g_idx[gq * K + lane] = ki;
            g_w[gq * K + lane]   = w;
        }
    } else {
        // ===================== transpose (fp16 store) ==============
        // (B,F,N) -> (B,N,F); tile = 32 f x 128 n per block
        float (*tile)[129] = (float (*)[129])smem_raw;   // 32*129*4 = 16512B

        int t  = blockIdx.x - KNNB;         // 0..2047
        int b  = t >> 9;                    // 512 tiles per batch
        int r  = t & 511;
        int fb = r >> 6;                    // 0..7  (f block of 32)
        int nb = r & 63;                    // 0..63 (n block of 128)

        int tx = threadIdx.x & 127;         // n within tile
        int ty = threadIdx.x >> 7;          // 0..3
        const float* src = feat + ((size_t)b * F + fb * 32) * N + nb * 128;
        #pragma unroll
        for (int j = ty; j < 32; j += 4)
            tile[j][tx] = src[(size_t)j * N + tx];
        __syncthreads();

        int cx = threadIdx.x & 31;          // f within tile
        int cy = threadIdx.x >> 5;          // 0..15
        __half* dst = g_featT + ((size_t)b * N + nb * 128) * F + fb * 32;
        #pragma unroll
        for (int j = cy; j < 128; j += 16)
            dst[(size_t)j * F + cx] = __float2half(tile[cx][j]);
    }
}

// ---------------------------------------------------------------------------
// Feature propagation: 1024 threads = 32 warps = 16 queries, 2 warps/query
// (proven shape). fp16 gathers: each lane reads 4 halves (8B) per neighbor
// — half the L2 sector traffic of fp32. Accumulation in fp32.
// ---------------------------------------------------------------------------
__global__ __launch_bounds__(1024) void feat_kernel(float* __restrict__ out)
{
    __shared__ float so[16][260];

    const int lane   = threadIdx.x & 31;
    const int wid    = threadIdx.x >> 5;       // 0..31
    const int qlocal = wid >> 1;               // 0..15
    const int half   = wid & 1;                // 0/1 -> 128 features each
    const int b      = blockIdx.x >> 7;        // 128 blocks per batch
    const int m0     = (blockIdx.x & 127) * 16;
    const int m      = m0 + qlocal;
    const size_t gq  = (size_t)b * M + m;

    int   iv = 0;
    float wv = 0.0f;
    if (lane < K) {
        iv = g_idx[gq * K + lane];
        wv = g_w[gq * K + lane];
    }

    float4 acc = make_float4(0.f, 0.f, 0.f, 0.f);
    #pragma unroll
    for (int j = 0; j < K; ++j) {
        float wj = __shfl_sync(FULL, wv, j);
        int   ij = __shfl_sync(FULL, iv, j);
        const __half* basep =
            g_featT + ((size_t)b * N + ij) * F + half * 128;
        uint2 raw = *(const uint2*)(basep + lane * 4);   // 4 halves, 8B aligned
        __half2 h01 = *reinterpret_cast<__half2*>(&raw.x);
        __half2 h23 = *reinterpret_cast<__half2*>(&raw.y);
        float2 f01 = __half22float2(h01);
        float2 f23 = __half22float2(h23);
        acc.x = fmaf(wj, f01.x, acc.x);
        acc.y = fmaf(wj, f01.y, acc.y);
        acc.z = fmaf(wj, f23.x, acc.z);
        acc.w = fmaf(wj, f23.y, acc.w);
    }

    *(float4*)&so[qlocal][half * 128 + 4 * lane] = acc;
    __syncthreads();

    // warp wid writes f rows [wid*8, wid*8+8); lanes: 2 f x 16 mLocal
    #pragma unroll
    for (int r = 0; r < 4; ++r) {
        int f  = wid * 8 + r * 2 + (lane >> 4);
        int ml = lane & 15;
        out[((size_t)b * OUTC + 3 + f) * M + m0 + ml] = so[ml][f];
    }
}

// ---------------------------------------------------------------------------
extern "C" void kernel_launch(void* const* d_in, const int* in_sizes, int n_in,
                              void* d_out, int out_size)
{
    const float* pc   = (const float*)d_in[0];  // point_cloud (B,3,N)
    const float* qc   = (const float*)d_in[1];  // query_cloud (B,3,M)
    const float* feat = (const float*)d_in[2];  // point_features (B,F,N)
    const float* temp = (const float*)d_in[3];  // temperature scalar
    float* out = (float*)d_out;

    fused_knn_transpose<<<KNNB + TRB, 512>>>(pc, qc, temp, feat, out);
    feat_kernel<<<(B * M) / 16, 1024>>>(out);
}